// round 4
// baseline (speedup 1.0000x reference)
// R3 resubmission: identical validated baseline (R2 run died on container infra,
// not kernel). Goal: obtain first passing measurement + ncu profile.
#include <cuda_runtime.h>

#define BB 64
#define KK 4096
#define DD 64
#define QQ 11
#define HH 128
#define NITER 3
#define CPB 8            // attention CTAs per batch
#define NACC 768         // padded per-CTA partial record (704 U + 11 S + 22 A1 + 22 A2)
#define TILE 128

// ---------------- scratch (static device memory; no allocations) ----------------
__device__ float g_k[BB * KK * DD];       // 64 MB
__device__ float g_v[BB * KK * DD];       // 64 MB
__device__ float g_grid[BB * KK * 2];
__device__ float g_slots[BB * QQ * DD];
__device__ float g_q[BB * QQ * DD];
__device__ float g_part[BB * CPB * NACC];

// ---------------- helpers ----------------
__device__ __forceinline__ float bsum64(float v, volatile float* red) {
    #pragma unroll
    for (int o = 16; o; o >>= 1) v += __shfl_xor_sync(0xffffffffu, v, o);
    int t = threadIdx.x;
    if ((t & 31) == 0) red[t >> 5] = v;
    __syncthreads();
    float r = red[0] + red[1];
    __syncthreads();
    return r;
}

// ================= Kernel 1: positional encode + 2x LayerNorm + K/V projection =================
// grid: BB*64 CTAs (64 rows each), 256 threads (8 warps, 8 rows/warp)
__global__ void __launch_bounds__(256) prep_kernel(
    const float* __restrict__ in, const float* __restrict__ Wpe, const float* __restrict__ bpe,
    const float* __restrict__ ges, const float* __restrict__ geb,
    const float* __restrict__ ins, const float* __restrict__ inb,
    const float* __restrict__ Wk, const float* __restrict__ Wv)
{
    __shared__ __align__(16) float sW[64 * 128];   // interleaved: cols 0..63 Wk, 64..127 Wv
    int t = threadIdx.x;
    int bid = blockIdx.x;
    int b = bid >> 6;
    int row0 = (bid & 63) * 64;

    for (int i = t; i < 64 * 128; i += 256) {
        int d = i >> 7, col = i & 127;
        sW[i] = (col < 64) ? Wk[d * 64 + col] : Wv[d * 64 + col - 64];
    }
    int lane = t & 31;
    int w = t >> 5;

    float pe00 = Wpe[lane],      pe01 = Wpe[32 + lane];
    float pe10 = Wpe[64 + lane], pe11 = Wpe[96 + lane];
    float bp0 = bpe[lane],  bp1 = bpe[32 + lane];
    float gs0 = ges[lane],  gs1 = ges[32 + lane];
    float gb0 = geb[lane],  gb1 = geb[32 + lane];
    float is0 = ins[lane],  is1 = ins[32 + lane];
    float ib0 = inb[lane],  ib1 = inb[32 + lane];
    __syncthreads();

    for (int r = 0; r < 8; ++r) {
        int row = row0 + w * 8 + r;
        const float* src = in + (size_t)(b * KK + row) * 66;
        float f0 = src[lane], f1 = src[32 + lane];
        float gx = src[64], gy = src[65];
        float x0 = f0 + gx * pe00 + gy * pe10 + bp0;
        float x1 = f1 + gx * pe01 + gy * pe11 + bp1;

        // LN1
        float s = x0 + x1;
        #pragma unroll
        for (int o = 16; o; o >>= 1) s += __shfl_xor_sync(0xffffffffu, s, o);
        float m = s * (1.f / 64.f);
        float d0 = x0 - m, d1 = x1 - m;
        float vv = d0 * d0 + d1 * d1;
        #pragma unroll
        for (int o = 16; o; o >>= 1) vv += __shfl_xor_sync(0xffffffffu, vv, o);
        float inv = rsqrtf(vv * (1.f / 64.f) + 1e-6f);
        x0 = d0 * inv * gs0 + gb0;
        x1 = d1 * inv * gs1 + gb1;

        // LN2
        s = x0 + x1;
        #pragma unroll
        for (int o = 16; o; o >>= 1) s += __shfl_xor_sync(0xffffffffu, s, o);
        m = s * (1.f / 64.f);
        d0 = x0 - m; d1 = x1 - m;
        vv = d0 * d0 + d1 * d1;
        #pragma unroll
        for (int o = 16; o; o >>= 1) vv += __shfl_xor_sync(0xffffffffu, vv, o);
        inv = rsqrtf(vv * (1.f / 64.f) + 1e-6f);
        x0 = d0 * inv * is0 + ib0;
        x1 = d1 * inv * is1 + ib1;

        // fused GEMV: lane computes 4 interleaved outputs (k row for lane<16, v row for lane>=16)
        float o0 = 0.f, o1 = 0.f, o2 = 0.f, o3 = 0.f;
        #pragma unroll
        for (int d = 0; d < 64; ++d) {
            float xd = __shfl_sync(0xffffffffu, (d < 32) ? x0 : x1, d & 31);
            float4 wv4 = *(const float4*)(sW + d * 128 + lane * 4);
            o0 += xd * wv4.x; o1 += xd * wv4.y; o2 += xd * wv4.z; o3 += xd * wv4.w;
        }
        size_t obase = (size_t)(b * KK + row) * 64;
        float4 ov = make_float4(o0, o1, o2, o3);
        if (lane < 16) *(float4*)(g_k + obase + lane * 4) = ov;
        else           *(float4*)(g_v + obase + (lane - 16) * 4) = ov;
        if (lane == 0) {
            g_grid[(b * KK + row) * 2]     = gx;
            g_grid[(b * KK + row) * 2 + 1] = gy;
        }
    }
}

// ================= Kernel 2: q = ln(slots) @ Wq * scale =================
// grid: B*Q blocks, 64 threads
__global__ void __launch_bounds__(64) q_kernel(
    const float* __restrict__ slots_in, const float* __restrict__ qs,
    const float* __restrict__ qb, const float* __restrict__ Wq, int it)
{
    __shared__ float xs[64];
    __shared__ float red[2];
    int row = blockIdx.x, t = threadIdx.x;
    float sv = (it == 0) ? slots_in[row * 68 + t] : g_slots[row * 64 + t];
    if (it == 0) g_slots[row * 64 + t] = sv;
    float m = bsum64(sv, red) * (1.f / 64.f);
    float dv = sv - m;
    float var = bsum64(dv * dv, red) * (1.f / 64.f);
    float xn = dv * rsqrtf(var + 1e-6f) * qs[t] + qb[t];
    xs[t] = xn;
    __syncthreads();
    float acc = 0.f;
    #pragma unroll
    for (int d = 0; d < 64; ++d) acc += xs[d] * Wq[d * 64 + t];
    g_q[row * 64 + t] = acc * 0.125f;   // 1/sqrt(64)
}

// ================= Kernel 3: streaming attention pass =================
// Per key: 11 logits, softmax over Q, accumulate U = sum a*v, S = sum a, moments with grid.
// grid: B*CPB CTAs, 128 threads. Deterministic split-K: each CTA writes its own partial slice.
__global__ void __launch_bounds__(128) attn_kernel(int last)
{
    __shared__ __align__(16) float sQ[704];
    __shared__ __align__(16) float sKV[128 * 68];
    __shared__ __align__(16) float sA[128 * 13];
    __shared__ __align__(16) float sG[256];
    int t = threadIdx.x;
    int b = blockIdx.x >> 3, c = blockIdx.x & 7;
    int key0 = c * 512;

    for (int i = t; i < 704; i += 128) sQ[i] = g_q[b * 704 + i];

    int dg = t & 31, qg = t >> 5;
    int qB = qg * 3;
    int nq = (qg == 3) ? 2 : 3;

    float aU[3][2] = {{0.f,0.f},{0.f,0.f},{0.f,0.f}};
    float sS[11];
    float a1x[11], a1y[11], a2x[11], a2y[11];
    #pragma unroll
    for (int i = 0; i < 11; i++) { sS[i]=0.f; a1x[i]=0.f; a1y[i]=0.f; a2x[i]=0.f; a2y[i]=0.f; }

    for (int tile = 0; tile < 4; ++tile) {
        int kb = key0 + tile * TILE;
        __syncthreads();
        // load K tile
        const float4* gk = (const float4*)(g_k + ((size_t)b * KK + kb) * 64);
        for (int i = t; i < 2048; i += 128)
            *((float4*)(sKV + (i >> 4) * 68) + (i & 15)) = gk[i];
        const float* gg = g_grid + ((size_t)b * KK + kb) * 2;
        for (int i = t; i < 256; i += 128) sG[i] = gg[i];
        __syncthreads();

        // logits for my key (=t) + softmax over 11 slots
        float l[11];
        #pragma unroll
        for (int i = 0; i < 11; i++) l[i] = 0.f;
        #pragma unroll 8
        for (int d = 0; d < 64; ++d) {
            float kd = sKV[t * 68 + d];
            #pragma unroll
            for (int qi = 0; qi < 11; qi++) l[qi] += sQ[qi * 64 + d] * kd;
        }
        float mx = l[0];
        #pragma unroll
        for (int i = 1; i < 11; i++) mx = fmaxf(mx, l[i]);
        float sum = 0.f;
        #pragma unroll
        for (int i = 0; i < 11; i++) { l[i] = __expf(l[i] - mx); sum += l[i]; }
        float inv = 1.f / sum;
        float gx = sG[t * 2], gy = sG[t * 2 + 1];
        float gxx = gx * gx, gyy = gy * gy;
        #pragma unroll
        for (int i = 0; i < 11; i++) {
            float a = l[i] * inv;
            sA[t * 13 + i] = a;
            sS[i] += a;
            if (last) { a1x[i] += a*gx; a1y[i] += a*gy; a2x[i] += a*gxx; a2y[i] += a*gyy; }
        }
        sA[t * 13 + 11] = 0.f;   // safe pad for qg==3 reads
        __syncthreads();

        // load V tile (reuse sKV)
        const float4* gv = (const float4*)(g_v + ((size_t)b * KK + kb) * 64);
        for (int i = t; i < 2048; i += 128)
            *((float4*)(sKV + (i >> 4) * 68) + (i & 15)) = gv[i];
        __syncthreads();

        // rank-1 accumulate: U[q][d] += a[key][q] * v[key][d], register-blocked 3q x 2d
        #pragma unroll 4
        for (int key = 0; key < TILE; ++key) {
            float a0 = sA[key * 13 + qB];
            float a1 = sA[key * 13 + qB + 1];
            float a2 = sA[key * 13 + qB + 2];
            float v0 = sKV[key * 68 + dg];
            float v1 = sKV[key * 68 + dg + 32];
            aU[0][0] += a0 * v0; aU[0][1] += a0 * v1;
            aU[1][0] += a1 * v0; aU[1][1] += a1 * v1;
            aU[2][0] += a2 * v0; aU[2][1] += a2 * v1;
        }
    }

    // epilogue: write partials (deterministic; each CTA owns its slice)
    __syncthreads();
    float* red = sKV;
    size_t base = ((size_t)b * CPB + c) * NACC;
    #pragma unroll
    for (int i = 0; i < 3; i++) {
        if (i < nq) {
            g_part[base + (qB + i) * 64 + dg]      = aU[i][0];
            g_part[base + (qB + i) * 64 + dg + 32] = aU[i][1];
        }
    }
    int w = t >> 5, lane = t & 31;
    #define RED1(v, slot) { float _x = (v); \
        _Pragma("unroll") for (int _o = 16; _o; _o >>= 1) _x += __shfl_xor_sync(0xffffffffu, _x, _o); \
        if (lane == 0) red[w * 64 + (slot)] = _x; }
    #pragma unroll
    for (int i = 0; i < 11; i++) RED1(sS[i], i);
    if (last) {
        #pragma unroll
        for (int i = 0; i < 11; i++) {
            RED1(a1x[i], 11 + i); RED1(a1y[i], 22 + i);
            RED1(a2x[i], 33 + i); RED1(a2y[i], 44 + i);
        }
    }
    #undef RED1
    __syncthreads();
    int nvals = last ? 55 : 11;
    if (t < nvals) {
        float tot = red[t] + red[64 + t] + red[128 + t] + red[192 + t];
        int off;
        if (t < 11)      off = 704 + t;
        else if (t < 22) off = 715 + (t - 11) * 2;
        else if (t < 33) off = 716 + (t - 22) * 2;
        else if (t < 44) off = 737 + (t - 33) * 2;
        else             off = 738 + (t - 44) * 2;
        g_part[base + off] = tot;
    }
}

// ================= Kernel 4: GRU + MLP slot update (+ final positions/scales) =================
// grid: B*Q blocks, 64 threads
__global__ void __launch_bounds__(64) upd_kernel(
    const float* __restrict__ Wir, const float* __restrict__ Wiz, const float* __restrict__ Win,
    const float* __restrict__ bir, const float* __restrict__ biz, const float* __restrict__ binp,
    const float* __restrict__ Whr, const float* __restrict__ Whz, const float* __restrict__ Whn,
    const float* __restrict__ bhn, const float* __restrict__ mls, const float* __restrict__ mlb,
    const float* __restrict__ W1, const float* __restrict__ b1,
    const float* __restrict__ W2, const float* __restrict__ b2,
    float* __restrict__ outp, int last)
{
    __shared__ float upd[64], sl[64], xn[64], hb[128];
    __shared__ float red[2];
    int bq = blockIdx.x, t = threadIdx.x;
    int b = bq / 11, q = bq - b * 11;
    const float* pb = g_part + (size_t)b * CPB * NACC;

    float U = 0.f, S = 0.f;
    #pragma unroll
    for (int cc = 0; cc < CPB; cc++) {
        U += pb[cc * NACC + q * 64 + t];
        S += pb[cc * NACC + 704 + q];
    }
    float u = U / (S + 1e-8f);
    upd[t] = u;
    sl[t] = g_slots[bq * 64 + t];
    __syncthreads();

    float air = bir[t], aiz = biz[t], ain = binp[t];
    float ahr = 0.f, ahz = 0.f, ahn = bhn[t];
    #pragma unroll 4
    for (int d = 0; d < 64; ++d) {
        float ud = upd[d], sd = sl[d];
        air += ud * Wir[d * 64 + t];
        aiz += ud * Wiz[d * 64 + t];
        ain += ud * Win[d * 64 + t];
        ahr += sd * Whr[d * 64 + t];
        ahz += sd * Whz[d * 64 + t];
        ahn += sd * Whn[d * 64 + t];
    }
    float r = 1.f / (1.f + __expf(-(air + ahr)));
    float z = 1.f / (1.f + __expf(-(aiz + ahz)));
    float n = tanhf(ain + r * ahn);
    float snew = (1.f - z) * n + z * sl[t];

    // MLP with residual
    float m = bsum64(snew, red) * (1.f / 64.f);
    float dv = snew - m;
    float var = bsum64(dv * dv, red) * (1.f / 64.f);
    float x = dv * rsqrtf(var + 1e-6f) * mls[t] + mlb[t];
    xn[t] = x;
    __syncthreads();
    float h0 = b1[t], h1 = b1[64 + t];
    #pragma unroll 4
    for (int d = 0; d < 64; ++d) {
        float xd = xn[d];
        h0 += xd * W1[d * 128 + t];
        h1 += xd * W1[d * 128 + 64 + t];
    }
    hb[t] = fmaxf(h0, 0.f);
    hb[64 + t] = fmaxf(h1, 0.f);
    __syncthreads();
    float od = snew + b2[t];
    #pragma unroll 4
    for (int hh = 0; hh < 128; ++hh) od += hb[hh] * W2[hh * 64 + t];

    if (!last) { g_slots[bq * 64 + t] = od; return; }

    // final output: slots + positions + scales
    outp[bq * 68 + t] = od;
    float s1x = 0.f, s1y = 0.f, s2x = 0.f, s2y = 0.f;
    const float2* gg = (const float2*)(g_grid + (size_t)b * KK * 2);
    for (int k = t; k < KK; k += 64) {
        float2 g = gg[k];
        s1x += g.x; s1y += g.y; s2x += g.x * g.x; s2y += g.y * g.y;
    }
    s1x = bsum64(s1x, red); s1y = bsum64(s1y, red);
    s2x = bsum64(s2x, red); s2y = bsum64(s2y, red);
    if (t == 0) {
        float A1xv = 0.f, A1yv = 0.f, A2xv = 0.f, A2yv = 0.f;
        #pragma unroll
        for (int cc = 0; cc < CPB; cc++) {
            A1xv += pb[cc * NACC + 715 + q * 2];
            A1yv += pb[cc * NACC + 716 + q * 2];
            A2xv += pb[cc * NACC + 737 + q * 2];
            A2yv += pb[cc * NACC + 738 + q * 2];
        }
        float inv = 1.f / (S + 1e-8f);
        float px = A1xv * inv, py = A1yv * inv;
        float T = S * inv;
        float vx = A2xv * inv - px * px * (2.f - T)
                 + 1e-8f * (s2x - 2.f * px * s1x + 4096.f * px * px);
        float vy = A2yv * inv - py * py * (2.f - T)
                 + 1e-8f * (s2y - 2.f * py * s1y + 4096.f * py * py);
        float scx = fminf(fmaxf(sqrtf(fmaxf(vx, 0.f)), 0.01f), 5.f);
        float scy = fminf(fmaxf(sqrtf(fmaxf(vy, 0.f)), 0.01f), 5.f);
        outp[bq * 68 + 64] = px;
        outp[bq * 68 + 65] = py;
        outp[bq * 68 + 66] = scx;
        outp[bq * 68 + 67] = scy;
    }
}

// ================= launch =================
extern "C" void kernel_launch(void* const* d_in, const int* in_sizes, int n_in,
                              void* d_out, int out_size)
{
    (void)in_sizes; (void)n_in; (void)out_size;
    const float* slots  = (const float*)d_in[0];
    const float* inputs = (const float*)d_in[1];
    const float* Wpe  = (const float*)d_in[2];
    const float* bpe  = (const float*)d_in[3];
    const float* ges  = (const float*)d_in[4];
    const float* geb  = (const float*)d_in[5];
    const float* ins  = (const float*)d_in[6];
    const float* inb  = (const float*)d_in[7];
    const float* Wk   = (const float*)d_in[8];
    const float* Wv   = (const float*)d_in[9];
    const float* qs   = (const float*)d_in[10];
    const float* qb   = (const float*)d_in[11];
    const float* Wq   = (const float*)d_in[12];
    const float* Wir  = (const float*)d_in[13];
    const float* Wiz  = (const float*)d_in[14];
    const float* Win  = (const float*)d_in[15];
    const float* bir  = (const float*)d_in[16];
    const float* biz  = (const float*)d_in[17];
    const float* binp = (const float*)d_in[18];
    const float* Whr  = (const float*)d_in[19];
    const float* Whz  = (const float*)d_in[20];
    const float* Whn  = (const float*)d_in[21];
    const float* bhn  = (const float*)d_in[22];
    const float* mls  = (const float*)d_in[23];
    const float* mlb  = (const float*)d_in[24];
    const float* W1   = (const float*)d_in[25];
    const float* b1   = (const float*)d_in[26];
    const float* W2   = (const float*)d_in[27];
    const float* b2   = (const float*)d_in[28];
    float* out = (float*)d_out;

    prep_kernel<<<BB * 64, 256>>>(inputs, Wpe, bpe, ges, geb, ins, inb, Wk, Wv);
    for (int it = 0; it < NITER; ++it) {
        int last = (it == NITER - 1);
        q_kernel<<<BB * QQ, 64>>>(slots, qs, qb, Wq, it);
        attn_kernel<<<BB * CPB, 128>>>(last);
        upd_kernel<<<BB * QQ, 64>>>(Wir, Wiz, Win, bir, biz, binp, Whr, Whz, Whn,
                                    bhn, mls, mlb, W1, b1, W2, b2, out, last);
    }
}

// round 5
// speedup vs baseline: 1.2061x; 1.2061x over previous
// R5: prep shuffle-GEMV -> smem GEMM (FMA-bound); upd -> 88x512 weight-staged
// blocks with fused next-iter q projection; attn -> 2 keys/thread + float4 logits.
#include <cuda_runtime.h>

#define BB 64
#define KK 4096
#define DD 64
#define QQ 11
#define HH 128
#define NITER 3
#define CPB 8            // attention CTAs per batch
#define NACC 768         // per-CTA partial record (704 U + 11 S + 22 A1 + 22 A2)

#define PREP_SMEM (12544 * 4)   // sW 8192 + sX 64*68
#define ATTN_SMEM (21952 * 4)   // sQ 704 + sKV 256*68 + sA 256*13 + sG 512
#define UPD_SMEM  (45056 * 4)   // 6x4096 GRU + W1 8192 + W2 8192 + Wq 4096

// ---------------- scratch (static device memory; no allocations) ----------------
__device__ __align__(16) float g_k[BB * KK * DD];
__device__ __align__(16) float g_v[BB * KK * DD];
__device__ __align__(16) float g_grid[BB * KK * 2];
__device__ __align__(16) float g_slots[BB * QQ * DD];
__device__ __align__(16) float g_q[BB * QQ * DD];
__device__ __align__(16) float g_part[BB * CPB * NACC];

// ---------------- helpers ----------------
__device__ __forceinline__ float bsum64(float v, volatile float* red) {
    #pragma unroll
    for (int o = 16; o; o >>= 1) v += __shfl_xor_sync(0xffffffffu, v, o);
    int t = threadIdx.x;
    if ((t & 31) == 0) red[t >> 5] = v;
    __syncthreads();
    float r = red[0] + red[1];
    __syncthreads();
    return r;
}

// per-row sum over 64 threads (2 warps) inside a 512-thread block
__device__ __forceinline__ float rowsum64(float v, int t, volatile float* red2) {
    #pragma unroll
    for (int o = 16; o; o >>= 1) v += __shfl_xor_sync(0xffffffffu, v, o);
    if ((t & 31) == 0) red2[t >> 5] = v;
    __syncthreads();
    float r = red2[0] + red2[1];
    __syncthreads();
    return r;
}

// ================= Kernel 1: PE + 2x LayerNorm + K/V projection (smem GEMM) ====
// grid: BB*64 CTAs (64 rows each), 256 threads
__global__ void __launch_bounds__(256) prep_kernel(
    const float* __restrict__ in, const float* __restrict__ Wpe, const float* __restrict__ bpe,
    const float* __restrict__ ges, const float* __restrict__ geb,
    const float* __restrict__ ins, const float* __restrict__ inb,
    const float* __restrict__ Wk, const float* __restrict__ Wv)
{
    extern __shared__ float dsm[];
    float* sW = dsm;              // [64 d][128 cols] cols 0..63 Wk, 64..127 Wv
    float* sX = dsm + 8192;       // [64 d][rows], stride 68

    int t = threadIdx.x;
    int bid = blockIdx.x;
    int b = bid >> 6;
    int row0 = (bid & 63) * 64;

    for (int i = t; i < 8192; i += 256) {
        int d = i >> 7, col = i & 127;
        sW[i] = (col < 64) ? Wk[d * 64 + col] : Wv[d * 64 + col - 64];
    }
    int lane = t & 31;
    int w = t >> 5;

    float pe00 = Wpe[lane],      pe01 = Wpe[32 + lane];
    float pe10 = Wpe[64 + lane], pe11 = Wpe[96 + lane];
    float bp0 = bpe[lane],  bp1 = bpe[32 + lane];
    float gs0 = ges[lane],  gs1 = ges[32 + lane];
    float gb0 = geb[lane],  gb1 = geb[32 + lane];
    float is0 = ins[lane],  is1 = ins[32 + lane];
    float ib0 = inb[lane],  ib1 = inb[32 + lane];

    // phase 1: LN pipeline, 8 warps x 8 rows, store x transposed into sX
    for (int r = 0; r < 8; ++r) {
        int lrow = w * 8 + r;
        int row = row0 + lrow;
        const float* src = in + (size_t)(b * KK + row) * 66;
        float f0 = src[lane], f1 = src[32 + lane];
        float gx = src[64], gy = src[65];
        float x0 = f0 + gx * pe00 + gy * pe10 + bp0;
        float x1 = f1 + gx * pe01 + gy * pe11 + bp1;

        // LN1
        float s = x0 + x1;
        #pragma unroll
        for (int o = 16; o; o >>= 1) s += __shfl_xor_sync(0xffffffffu, s, o);
        float m = s * (1.f / 64.f);
        float d0 = x0 - m, d1 = x1 - m;
        float vv = d0 * d0 + d1 * d1;
        #pragma unroll
        for (int o = 16; o; o >>= 1) vv += __shfl_xor_sync(0xffffffffu, vv, o);
        float inv = rsqrtf(vv * (1.f / 64.f) + 1e-6f);
        x0 = d0 * inv * gs0 + gb0;
        x1 = d1 * inv * gs1 + gb1;

        // LN2
        s = x0 + x1;
        #pragma unroll
        for (int o = 16; o; o >>= 1) s += __shfl_xor_sync(0xffffffffu, s, o);
        m = s * (1.f / 64.f);
        d0 = x0 - m; d1 = x1 - m;
        vv = d0 * d0 + d1 * d1;
        #pragma unroll
        for (int o = 16; o; o >>= 1) vv += __shfl_xor_sync(0xffffffffu, vv, o);
        inv = rsqrtf(vv * (1.f / 64.f) + 1e-6f);
        x0 = d0 * inv * is0 + ib0;
        x1 = d1 * inv * is1 + ib1;

        sX[lane * 68 + lrow]        = x0;
        sX[(lane + 32) * 68 + lrow] = x1;
        if (lane == 0) {
            g_grid[(b * KK + row) * 2]     = gx;
            g_grid[(b * KK + row) * 2 + 1] = gy;
        }
    }
    __syncthreads();

    // phase 2: GEMM [64 rows x 64 d] @ [64 d x 128 cols], 4 rows x 8 cols / thread
    int cg = t & 15, rg = t >> 4;
    int c0 = cg * 8, r0 = rg * 4;
    float acc[4][8];
    #pragma unroll
    for (int i = 0; i < 4; i++)
        #pragma unroll
        for (int j = 0; j < 8; j++) acc[i][j] = 0.f;

    #pragma unroll 4
    for (int d = 0; d < 64; ++d) {
        float xv0 = sX[d * 68 + r0];
        float xv1 = sX[d * 68 + r0 + 1];
        float xv2 = sX[d * 68 + r0 + 2];
        float xv3 = sX[d * 68 + r0 + 3];
        float4 wa = *(const float4*)(sW + d * 128 + c0);
        float4 wb = *(const float4*)(sW + d * 128 + c0 + 4);
        acc[0][0] += xv0 * wa.x; acc[0][1] += xv0 * wa.y; acc[0][2] += xv0 * wa.z; acc[0][3] += xv0 * wa.w;
        acc[0][4] += xv0 * wb.x; acc[0][5] += xv0 * wb.y; acc[0][6] += xv0 * wb.z; acc[0][7] += xv0 * wb.w;
        acc[1][0] += xv1 * wa.x; acc[1][1] += xv1 * wa.y; acc[1][2] += xv1 * wa.z; acc[1][3] += xv1 * wa.w;
        acc[1][4] += xv1 * wb.x; acc[1][5] += xv1 * wb.y; acc[1][6] += xv1 * wb.z; acc[1][7] += xv1 * wb.w;
        acc[2][0] += xv2 * wa.x; acc[2][1] += xv2 * wa.y; acc[2][2] += xv2 * wa.z; acc[2][3] += xv2 * wa.w;
        acc[2][4] += xv2 * wb.x; acc[2][5] += xv2 * wb.y; acc[2][6] += xv2 * wb.z; acc[2][7] += xv2 * wb.w;
        acc[3][0] += xv3 * wa.x; acc[3][1] += xv3 * wa.y; acc[3][2] += xv3 * wa.z; acc[3][3] += xv3 * wa.w;
        acc[3][4] += xv3 * wb.x; acc[3][5] += xv3 * wb.y; acc[3][6] += xv3 * wb.z; acc[3][7] += xv3 * wb.w;
    }

    size_t gbase = (size_t)(b * KK + row0 + r0) * 64;
    #pragma unroll
    for (int i = 0; i < 4; i++) {
        float4 va = make_float4(acc[i][0], acc[i][1], acc[i][2], acc[i][3]);
        float4 vb = make_float4(acc[i][4], acc[i][5], acc[i][6], acc[i][7]);
        size_t off = gbase + (size_t)i * 64;
        if (cg < 8) {
            *(float4*)(g_k + off + c0)     = va;
            *(float4*)(g_k + off + c0 + 4) = vb;
        } else {
            *(float4*)(g_v + off + c0 - 64) = va;
            *(float4*)(g_v + off + c0 - 60) = vb;
        }
    }
}

// ================= Kernel 2: iter-0 q = ln(slots) @ Wq * scale =================
__global__ void __launch_bounds__(64) q_kernel(
    const float* __restrict__ slots_in, const float* __restrict__ qs,
    const float* __restrict__ qb, const float* __restrict__ Wq)
{
    __shared__ float xs[64];
    __shared__ float red[2];
    int row = blockIdx.x, t = threadIdx.x;
    float sv = slots_in[row * 68 + t];
    g_slots[row * 64 + t] = sv;
    float m = bsum64(sv, red) * (1.f / 64.f);
    float dv = sv - m;
    float var = bsum64(dv * dv, red) * (1.f / 64.f);
    float xn = dv * rsqrtf(var + 1e-6f) * qs[t] + qb[t];
    xs[t] = xn;
    __syncthreads();
    float acc = 0.f;
    #pragma unroll
    for (int d = 0; d < 64; ++d) acc += xs[d] * Wq[d * 64 + t];
    g_q[row * 64 + t] = acc * 0.125f;
}

// ================= Kernel 3: streaming attention pass ===========================
// grid: B*CPB = 512 CTAs, 128 threads, 2 keys/thread, TILE=256, 2 tiles.
__global__ void __launch_bounds__(128) attn_kernel(int last)
{
    extern __shared__ float dsm[];
    float* sQ  = dsm;                    // 704
    float* sKV = dsm + 704;              // 256*68
    float* sA  = dsm + 704 + 17408;      // 256*13
    float* sG  = dsm + 704 + 17408 + 3328; // 512

    int t = threadIdx.x;
    int b = blockIdx.x >> 3, c = blockIdx.x & 7;
    int key0 = c * 512;

    for (int i = t; i < 704; i += 128) sQ[i] = g_q[b * 704 + i];

    int dg = t & 31, qg = t >> 5;
    int qB = qg * 3;
    int nq = (qg == 3) ? 2 : 3;

    float aU[3][2] = {{0.f,0.f},{0.f,0.f},{0.f,0.f}};
    float sS[11];
    float a1x[11], a1y[11], a2x[11], a2y[11];
    #pragma unroll
    for (int i = 0; i < 11; i++) { sS[i]=0.f; a1x[i]=0.f; a1y[i]=0.f; a2x[i]=0.f; a2y[i]=0.f; }

    for (int tile = 0; tile < 2; ++tile) {
        int kb = key0 + tile * 256;
        __syncthreads();
        // K tile (256 rows x 16 float4)
        const float4* gk = (const float4*)(g_k + ((size_t)b * KK + kb) * 64);
        for (int i = t; i < 4096; i += 128)
            *((float4*)(sKV + (i >> 4) * 68) + (i & 15)) = gk[i];
        const float4* gg = (const float4*)(g_grid + ((size_t)b * KK + kb) * 2);
        for (int i = t; i < 128; i += 128) ((float4*)sG)[i] = gg[i];
        __syncthreads();

        // logits for keys t and t+128, float4 over d
        float l0[11], l1[11];
        #pragma unroll
        for (int i = 0; i < 11; i++) { l0[i] = 0.f; l1[i] = 0.f; }
        #pragma unroll 2
        for (int d4 = 0; d4 < 16; ++d4) {
            float4 k0 = *(const float4*)(sKV + t * 68 + d4 * 4);
            float4 k1 = *(const float4*)(sKV + (t + 128) * 68 + d4 * 4);
            #pragma unroll
            for (int qi = 0; qi < 11; qi++) {
                float4 qv = *(const float4*)(sQ + qi * 64 + d4 * 4);
                l0[qi] += qv.x * k0.x + qv.y * k0.y + qv.z * k0.z + qv.w * k0.w;
                l1[qi] += qv.x * k1.x + qv.y * k1.y + qv.z * k1.z + qv.w * k1.w;
            }
        }
        // softmax over 11 slots (per key)
        float mx0 = l0[0], mx1 = l1[0];
        #pragma unroll
        for (int i = 1; i < 11; i++) { mx0 = fmaxf(mx0, l0[i]); mx1 = fmaxf(mx1, l1[i]); }
        float sum0 = 0.f, sum1 = 0.f;
        #pragma unroll
        for (int i = 0; i < 11; i++) {
            l0[i] = __expf(l0[i] - mx0); sum0 += l0[i];
            l1[i] = __expf(l1[i] - mx1); sum1 += l1[i];
        }
        float inv0 = 1.f / sum0, inv1 = 1.f / sum1;
        float gx0 = sG[2 * t], gy0 = sG[2 * t + 1];
        float gx1 = sG[2 * (t + 128)], gy1 = sG[2 * (t + 128) + 1];
        float gxx0 = gx0 * gx0, gyy0 = gy0 * gy0;
        float gxx1 = gx1 * gx1, gyy1 = gy1 * gy1;
        #pragma unroll
        for (int i = 0; i < 11; i++) {
            float a0 = l0[i] * inv0;
            float a1 = l1[i] * inv1;
            sA[t * 13 + i]         = a0;
            sA[(t + 128) * 13 + i] = a1;
            sS[i] += a0 + a1;
            if (last) {
                a1x[i] += a0 * gx0 + a1 * gx1;
                a1y[i] += a0 * gy0 + a1 * gy1;
                a2x[i] += a0 * gxx0 + a1 * gxx1;
                a2y[i] += a0 * gyy0 + a1 * gyy1;
            }
        }
        sA[t * 13 + 11] = 0.f;
        sA[(t + 128) * 13 + 11] = 0.f;
        __syncthreads();

        // V tile (reuse sKV)
        const float4* gv = (const float4*)(g_v + ((size_t)b * KK + kb) * 64);
        for (int i = t; i < 4096; i += 128)
            *((float4*)(sKV + (i >> 4) * 68) + (i & 15)) = gv[i];
        __syncthreads();

        // rank-1 accumulate: U[q][d] += a[key][q] * v[key][d]
        #pragma unroll 4
        for (int key = 0; key < 256; ++key) {
            float a0 = sA[key * 13 + qB];
            float a1 = sA[key * 13 + qB + 1];
            float a2 = sA[key * 13 + qB + 2];
            float v0 = sKV[key * 68 + dg];
            float v1 = sKV[key * 68 + dg + 32];
            aU[0][0] += a0 * v0; aU[0][1] += a0 * v1;
            aU[1][0] += a1 * v0; aU[1][1] += a1 * v1;
            aU[2][0] += a2 * v0; aU[2][1] += a2 * v1;
        }
    }

    __syncthreads();
    float* red = sKV;
    size_t base = ((size_t)b * CPB + c) * NACC;
    #pragma unroll
    for (int i = 0; i < 3; i++) {
        if (i < nq) {
            g_part[base + (qB + i) * 64 + dg]      = aU[i][0];
            g_part[base + (qB + i) * 64 + dg + 32] = aU[i][1];
        }
    }
    int w = t >> 5, lane = t & 31;
    #define RED1(v, slot) { float _x = (v); \
        _Pragma("unroll") for (int _o = 16; _o; _o >>= 1) _x += __shfl_xor_sync(0xffffffffu, _x, _o); \
        if (lane == 0) red[w * 64 + (slot)] = _x; }
    #pragma unroll
    for (int i = 0; i < 11; i++) RED1(sS[i], i);
    if (last) {
        #pragma unroll
        for (int i = 0; i < 11; i++) {
            RED1(a1x[i], 11 + i); RED1(a1y[i], 22 + i);
            RED1(a2x[i], 33 + i); RED1(a2y[i], 44 + i);
        }
    }
    #undef RED1
    __syncthreads();
    int nvals = last ? 55 : 11;
    if (t < nvals) {
        float tot = red[t] + red[64 + t] + red[128 + t] + red[192 + t];
        int off;
        if (t < 11)      off = 704 + t;
        else if (t < 22) off = 715 + (t - 11) * 2;
        else if (t < 33) off = 716 + (t - 22) * 2;
        else if (t < 44) off = 737 + (t - 33) * 2;
        else             off = 738 + (t - 44) * 2;
        g_part[base + off] = tot;
    }
}

// ================= Kernel 4: GRU + MLP update (+ fused q / final stats) =========
// grid: 88 blocks x 512 threads, 8 rows/block, weights in 176KB dynamic smem
__global__ void __launch_bounds__(512) upd_kernel(
    const float* __restrict__ Wir, const float* __restrict__ Wiz, const float* __restrict__ Win,
    const float* __restrict__ bir, const float* __restrict__ biz, const float* __restrict__ binp,
    const float* __restrict__ Whr, const float* __restrict__ Whz, const float* __restrict__ Whn,
    const float* __restrict__ bhn, const float* __restrict__ mls, const float* __restrict__ mlb,
    const float* __restrict__ W1, const float* __restrict__ b1,
    const float* __restrict__ W2, const float* __restrict__ b2,
    const float* __restrict__ Wq, const float* __restrict__ qs, const float* __restrict__ qb,
    float* __restrict__ outp, int last)
{
    extern __shared__ float ws[];   // [Wir|Wiz|Win|Whr|Whz|Whn|W1|W2|Wq]
    __shared__ float s_upd[8][64], s_sl[8][64], s_xn[8][64], s_hb[8][128];
    __shared__ float s_red[8][2];

    int tid = threadIdx.x;
    for (int i = tid; i < 11264; i += 512) {
        float4 val;
        if      (i < 1024)  val = ((const float4*)Wir)[i];
        else if (i < 2048)  val = ((const float4*)Wiz)[i - 1024];
        else if (i < 3072)  val = ((const float4*)Win)[i - 2048];
        else if (i < 4096)  val = ((const float4*)Whr)[i - 3072];
        else if (i < 5120)  val = ((const float4*)Whz)[i - 4096];
        else if (i < 6144)  val = ((const float4*)Whn)[i - 5120];
        else if (i < 8192)  val = ((const float4*)W1)[i - 6144];
        else if (i < 10240) val = ((const float4*)W2)[i - 8192];
        else                val = ((const float4*)Wq)[i - 10240];
        ((float4*)ws)[i] = val;
    }

    int r = tid >> 6, t = tid & 63;
    int bq = blockIdx.x * 8 + r;
    int b = bq / 11, q = bq - b * 11;
    const float* pb = g_part + (size_t)b * CPB * NACC;

    float U = 0.f, S = 0.f;
    #pragma unroll
    for (int cc = 0; cc < CPB; cc++) {
        U += pb[cc * NACC + q * 64 + t];
        S += pb[cc * NACC + 704 + q];
    }
    float u = U / (S + 1e-8f);
    s_upd[r][t] = u;
    float slv = g_slots[bq * 64 + t];
    s_sl[r][t] = slv;
    __syncthreads();   // covers ws staging too

    float air = bir[t], aiz = biz[t], ain = binp[t];
    float ahr = 0.f, ahz = 0.f, ahn = bhn[t];
    const float* wir = ws;
    const float* wiz = ws + 4096;
    const float* win = ws + 8192;
    const float* whr = ws + 12288;
    const float* whz = ws + 16384;
    const float* whn = ws + 20480;
    #pragma unroll 4
    for (int d = 0; d < 64; ++d) {
        float ud = s_upd[r][d], sd = s_sl[r][d];
        air += ud * wir[d * 64 + t];
        aiz += ud * wiz[d * 64 + t];
        ain += ud * win[d * 64 + t];
        ahr += sd * whr[d * 64 + t];
        ahz += sd * whz[d * 64 + t];
        ahn += sd * whn[d * 64 + t];
    }
    float rg = 1.f / (1.f + __expf(-(air + ahr)));
    float zg = 1.f / (1.f + __expf(-(aiz + ahz)));
    float ng = tanhf(ain + rg * ahn);
    float snew = (1.f - zg) * ng + zg * slv;

    // MLP with residual
    float m = rowsum64(snew, t, s_red[r]) * (1.f / 64.f);
    float dv = snew - m;
    float var = rowsum64(dv * dv, t, s_red[r]) * (1.f / 64.f);
    float x = dv * rsqrtf(var + 1e-6f) * mls[t] + mlb[t];
    s_xn[r][t] = x;
    __syncthreads();
    const float* w1 = ws + 24576;
    float h0 = b1[t], h1 = b1[64 + t];
    #pragma unroll 4
    for (int d = 0; d < 64; ++d) {
        float xd = s_xn[r][d];
        h0 += xd * w1[d * 128 + t];
        h1 += xd * w1[d * 128 + 64 + t];
    }
    s_hb[r][t] = fmaxf(h0, 0.f);
    s_hb[r][64 + t] = fmaxf(h1, 0.f);
    __syncthreads();
    const float* w2 = ws + 32768;
    float od = snew + b2[t];
    #pragma unroll 4
    for (int hh = 0; hh < 128; ++hh) od += s_hb[r][hh] * w2[hh * 64 + t];

    if (!last) {
        g_slots[bq * 64 + t] = od;
        // fused q-projection for next iteration
        float qm = rowsum64(od, t, s_red[r]) * (1.f / 64.f);
        float qd = od - qm;
        float qvar = rowsum64(qd * qd, t, s_red[r]) * (1.f / 64.f);
        float xq = qd * rsqrtf(qvar + 1e-6f) * qs[t] + qb[t];
        s_xn[r][t] = xq;
        __syncthreads();
        const float* wq = ws + 40960;
        float acc = 0.f;
        #pragma unroll 4
        for (int d = 0; d < 64; ++d) acc += s_xn[r][d] * wq[d * 64 + t];
        g_q[bq * 64 + t] = acc * 0.125f;
        return;
    }

    // final output: slots + positions + scales
    outp[bq * 68 + t] = od;
    float s1x = 0.f, s1y = 0.f, s2x = 0.f, s2y = 0.f;
    const float2* gg = (const float2*)(g_grid + (size_t)b * KK * 2);
    for (int k = t; k < KK; k += 64) {
        float2 g = gg[k];
        s1x += g.x; s1y += g.y; s2x += g.x * g.x; s2y += g.y * g.y;
    }
    s1x = rowsum64(s1x, t, s_red[r]); s1y = rowsum64(s1y, t, s_red[r]);
    s2x = rowsum64(s2x, t, s_red[r]); s2y = rowsum64(s2y, t, s_red[r]);
    if (t == 0) {
        float A1xv = 0.f, A1yv = 0.f, A2xv = 0.f, A2yv = 0.f;
        #pragma unroll
        for (int cc = 0; cc < CPB; cc++) {
            A1xv += pb[cc * NACC + 715 + q * 2];
            A1yv += pb[cc * NACC + 716 + q * 2];
            A2xv += pb[cc * NACC + 737 + q * 2];
            A2yv += pb[cc * NACC + 738 + q * 2];
        }
        float inv = 1.f / (S + 1e-8f);
        float px = A1xv * inv, py = A1yv * inv;
        float T = S * inv;
        float vx = A2xv * inv - px * px * (2.f - T)
                 + 1e-8f * (s2x - 2.f * px * s1x + 4096.f * px * px);
        float vy = A2yv * inv - py * py * (2.f - T)
                 + 1e-8f * (s2y - 2.f * py * s1y + 4096.f * py * py);
        float scx = fminf(fmaxf(sqrtf(fmaxf(vx, 0.f)), 0.01f), 5.f);
        float scy = fminf(fmaxf(sqrtf(fmaxf(vy, 0.f)), 0.01f), 5.f);
        outp[bq * 68 + 64] = px;
        outp[bq * 68 + 65] = py;
        outp[bq * 68 + 66] = scx;
        outp[bq * 68 + 67] = scy;
    }
}

// ================= launch =================
extern "C" void kernel_launch(void* const* d_in, const int* in_sizes, int n_in,
                              void* d_out, int out_size)
{
    (void)in_sizes; (void)n_in; (void)out_size;
    const float* slots  = (const float*)d_in[0];
    const float* inputs = (const float*)d_in[1];
    const float* Wpe  = (const float*)d_in[2];
    const float* bpe  = (const float*)d_in[3];
    const float* ges  = (const float*)d_in[4];
    const float* geb  = (const float*)d_in[5];
    const float* ins  = (const float*)d_in[6];
    const float* inb  = (const float*)d_in[7];
    const float* Wk   = (const float*)d_in[8];
    const float* Wv   = (const float*)d_in[9];
    const float* qs   = (const float*)d_in[10];
    const float* qb   = (const float*)d_in[11];
    const float* Wq   = (const float*)d_in[12];
    const float* Wir  = (const float*)d_in[13];
    const float* Wiz  = (const float*)d_in[14];
    const float* Win  = (const float*)d_in[15];
    const float* bir  = (const float*)d_in[16];
    const float* biz  = (const float*)d_in[17];
    const float* binp = (const float*)d_in[18];
    const float* Whr  = (const float*)d_in[19];
    const float* Whz  = (const float*)d_in[20];
    const float* Whn  = (const float*)d_in[21];
    const float* bhn  = (const float*)d_in[22];
    const float* mls  = (const float*)d_in[23];
    const float* mlb  = (const float*)d_in[24];
    const float* W1   = (const float*)d_in[25];
    const float* b1   = (const float*)d_in[26];
    const float* W2   = (const float*)d_in[27];
    const float* b2   = (const float*)d_in[28];
    float* out = (float*)d_out;

    cudaFuncSetAttribute(prep_kernel, cudaFuncAttributeMaxDynamicSharedMemorySize, PREP_SMEM);
    cudaFuncSetAttribute(attn_kernel, cudaFuncAttributeMaxDynamicSharedMemorySize, ATTN_SMEM);
    cudaFuncSetAttribute(upd_kernel,  cudaFuncAttributeMaxDynamicSharedMemorySize, UPD_SMEM);

    prep_kernel<<<BB * 64, 256, PREP_SMEM>>>(inputs, Wpe, bpe, ges, geb, ins, inb, Wk, Wv);
    q_kernel<<<BB * QQ, 64>>>(slots, qs, qb, Wq);
    for (int it = 0; it < NITER; ++it) {
        int last = (it == NITER - 1);
        attn_kernel<<<BB * CPB, 128, ATTN_SMEM>>>(last);
        upd_kernel<<<BB * QQ / 8, 512, UPD_SMEM>>>(Wir, Wiz, Win, bir, biz, binp,
                                                   Whr, Whz, Whn, bhn, mls, mlb,
                                                   W1, b1, W2, b2, Wq, qs, qb, out, last);
    }
}